// round 3
// baseline (speedup 1.0000x reference)
#include <cuda_runtime.h>
#include <cstdint>

#define B_SIZE 4096
#define T_LEN  2048
#define H_DIM  32
#define THREADS 256
#define WARPS  (THREADS/32)
#define GRID   152

typedef unsigned long long ull;

__device__ int g_task_counter;

// ---- packed f32x2 helpers ----
__device__ __forceinline__ ull pk2(float a, float b) {
    ull r; asm("mov.b64 %0, {%1, %2};" : "=l"(r) : "f"(a), "f"(b)); return r;
}
__device__ __forceinline__ void upk2(ull v, float& a, float& b) {
    asm("mov.b64 {%0, %1}, %2;" : "=f"(a), "=f"(b) : "l"(v));
}
__device__ __forceinline__ void ffma2(ull& d, ull a, ull b) {
    asm("fma.rn.f32x2 %0, %1, %2, %0;" : "+l"(d) : "l"(a), "l"(b));
}

// ---- fast transcendentals (MUFU) ----
__device__ __forceinline__ float ex2f(float x) {
    float r; asm("ex2.approx.f32 %0, %1;" : "=f"(r) : "f"(x)); return r;
}
__device__ __forceinline__ float rcpf(float x) {
    float r; asm("rcp.approx.f32 %0, %1;" : "=f"(r) : "f"(x)); return r;
}
#define L2E 1.4426950408889634f
__device__ __forceinline__ float sigf(float z)  { return rcpf(1.f + ex2f(-L2E * z)); }
__device__ __forceinline__ float tanhf_(float z){ return fmaf(-2.f, rcpf(1.f + ex2f(2.f * L2E * z)), 1.f); }

// One LSTM step for slot S: reads hb<S>[pb<S>..], updates c<S>, flips pb<S>,
// stores new h. Uses register weight arrays wI/wF/wG/wO from enclosing scope.
#define LSTM_STEP(S) do {                                                     \
    ull ai = pk2(fmaf(xv##S, wxi, bci), 0.f);                                 \
    ull af = pk2(fmaf(xv##S, wxf, bcf), 0.f);                                 \
    ull ag = pk2(fmaf(xv##S, wxg, bcg), 0.f);                                 \
    ull ao = pk2(fmaf(xv##S, wxo, bco), 0.f);                                 \
    const ulonglong2* hp = (const ulonglong2*)(hb##S + pb##S);                \
    _Pragma("unroll")                                                         \
    for (int j = 0; j < 8; j++) {                                             \
        ulonglong2 q = hp[j];                                                 \
        ffma2(ai, wI[2*j],   q.x); ffma2(af, wF[2*j],   q.x);                 \
        ffma2(ag, wG[2*j],   q.x); ffma2(ao, wO[2*j],   q.x);                 \
        ffma2(ai, wI[2*j+1], q.y); ffma2(af, wF[2*j+1], q.y);                 \
        ffma2(ag, wG[2*j+1], q.y); ffma2(ao, wO[2*j+1], q.y);                 \
    }                                                                         \
    float e0, e1;                                                             \
    upk2(ai, e0, e1); const float gi = e0 + e1;                               \
    upk2(af, e0, e1); const float gf = e0 + e1;                               \
    upk2(ag, e0, e1); const float gg = e0 + e1;                               \
    upk2(ao, e0, e1); const float go = e0 + e1;                               \
    const float iv = sigf(gi);                                                \
    const float fv = sigf(gf);                                                \
    const float gv = tanhf_(gg);                                              \
    const float ov = sigf(go);                                                \
    c##S = fmaf(fv, c##S, iv * gv);                                           \
    const float hn = ov * tanhf_(c##S);                                       \
    pb##S ^= 32;                                                              \
    hb##S[pb##S + lane] = hn;                                                 \
} while (0)

// FC head + output write for slot S (final h is hb<S>[pb<S>..]).
#define FINISH(S) do {                                                        \
    float u0 = fcb0, u1 = fcb1;                                               \
    _Pragma("unroll")                                                         \
    for (int k = 0; k < 32; k++) {                                            \
        const float hk = hb##S[pb##S + k];                                    \
        u0 = fmaf(s_fcwT[k * 64 + lane],      hk, u0);                        \
        u1 = fmaf(s_fcwT[k * 64 + 32 + lane], hk, u1);                        \
    }                                                                         \
    u0 = (u0 > 0.f) ? u0 : (ex2f(L2E * u0) - 1.f);                            \
    u1 = (u1 > 0.f) ? u1 : (ex2f(L2E * u1) - 1.f);                            \
    float part = u0 * s_fc2[lane] + u1 * s_fc2[32 + lane];                    \
    _Pragma("unroll")                                                         \
    for (int s = 16; s; s >>= 1) part += __shfl_xor_sync(0xffffffffu, part, s); \
    if (lane == 0) out[task##S] = sigf(part + fc2b0);                         \
} while (0)

// Fetch a new sequence into slot S (or deactivate if tasks exhausted).
#define REFILL(S) do {                                                        \
    unsigned tk = 0;                                                          \
    if (lane == 0) tk = (unsigned)atomicAdd(&g_task_counter, 1);              \
    tk = __shfl_sync(0xffffffffu, tk, 0);                                     \
    if (tk >= B_SIZE) { act##S = false; }                                     \
    else {                                                                    \
        act##S = true; task##S = tk;                                          \
        t##S = lengths[tk] - 1;                                               \
        xb##S = x + (size_t)tk * T_LEN;                                       \
        c##S = 0.f; pb##S = 0;                                                \
        hb##S[lane] = 0.f;                                                    \
        xv##S = __ldg(xb##S + t##S);                                          \
        __syncwarp();                                                         \
    }                                                                         \
} while (0)

__global__ void __launch_bounds__(THREADS, 1)
bilstm_kernel(const float* __restrict__ x,
              const int*   __restrict__ lengths,
              const float* __restrict__ w_ih,
              const float* __restrict__ w_hh,
              const float* __restrict__ b_ih,
              const float* __restrict__ b_hh,
              const float* __restrict__ fc_w,
              const float* __restrict__ fc_b,
              const float* __restrict__ fc2_w,
              const float* __restrict__ fc2_b,
              float* __restrict__ out)
{
    __shared__ float s_fcwT[32 * 64];   // fc_w transposed: [k][r]
    __shared__ float s_fc2[64];
    __shared__ __align__(16) float s_h[WARPS * 128];  // 2 slots x 64 per warp

    const int tid  = threadIdx.x;
    const int lane = tid & 31;
    const int wid  = tid >> 5;

    for (int i = tid; i < 32 * 64; i += THREADS) {
        int r = i & 63, k = i >> 6;
        s_fcwT[i] = fc_w[r * 32 + k];
    }
    if (tid < 64) s_fc2[tid] = fc2_w[tid];
    __syncthreads();

    // ---- per-lane recurrent weights in registers (shared by both slots) ----
    const int l = lane;
    const float bci = b_ih[l]      + b_hh[l];
    const float bcf = b_ih[32 + l] + b_hh[32 + l];
    const float bcg = b_ih[64 + l] + b_hh[64 + l];
    const float bco = b_ih[96 + l] + b_hh[96 + l];
    const float wxi = w_ih[l], wxf = w_ih[32 + l], wxg = w_ih[64 + l], wxo = w_ih[96 + l];

    ull wI[16], wF[16], wG[16], wO[16];
    {
        const ull* pI = (const ull*)(w_hh + (0  + l) * H_DIM);
        const ull* pF = (const ull*)(w_hh + (32 + l) * H_DIM);
        const ull* pG = (const ull*)(w_hh + (64 + l) * H_DIM);
        const ull* pO = (const ull*)(w_hh + (96 + l) * H_DIM);
        #pragma unroll
        for (int j = 0; j < 16; j++) { wI[j] = pI[j]; wF[j] = pF[j]; wG[j] = pG[j]; wO[j] = pO[j]; }
    }
    const float fc2b0 = fc2_b[0];
    const float fcb0  = fc_b[l];
    const float fcb1  = fc_b[32 + l];

    float* hb0 = s_h + wid * 128;
    float* hb1 = hb0 + 64;

    // ---- two independent sequence slots per warp ----
    bool act0 = false, act1 = false;
    unsigned task0 = 0, task1 = 0;
    int t0 = -1, t1 = -1, pb0 = 0, pb1 = 0;
    float c0 = 0.f, c1 = 0.f, xv0 = 0.f, xv1 = 0.f;
    const float* xb0 = x; const float* xb1 = x;

    REFILL(0);
    REFILL(1);

    for (;;) {
        if (act0 && act1) {
            // dual-issue: two independent recurrences hide each other's latency
            while (t0 >= 0 && t1 >= 0) {
                float xn0 = __ldg(xb0 + ((t0 > 0) ? t0 - 1 : 0));
                float xn1 = __ldg(xb1 + ((t1 > 0) ? t1 - 1 : 0));
                LSTM_STEP(0);
                LSTM_STEP(1);
                __syncwarp();
                xv0 = xn0; xv1 = xn1;
                --t0; --t1;
            }
        } else if (act0) {
            while (t0 >= 0) {
                float xn0 = __ldg(xb0 + ((t0 > 0) ? t0 - 1 : 0));
                LSTM_STEP(0);
                __syncwarp();
                xv0 = xn0;
                --t0;
            }
        } else if (act1) {
            while (t1 >= 0) {
                float xn1 = __ldg(xb1 + ((t1 > 0) ? t1 - 1 : 0));
                LSTM_STEP(1);
                __syncwarp();
                xv1 = xn1;
                --t1;
            }
        } else {
            break;
        }
        if (act0 && t0 < 0) { FINISH(0); REFILL(0); }
        if (act1 && t1 < 0) { FINISH(1); REFILL(1); }
    }
}

__global__ void reset_counter_kernel() { g_task_counter = 0; }

extern "C" void kernel_launch(void* const* d_in, const int* in_sizes, int n_in,
                              void* d_out, int out_size)
{
    const float* x       = (const float*)d_in[0];
    const int*   lengths = (const int*)  d_in[1];
    const float* w_ih    = (const float*)d_in[2];
    const float* w_hh    = (const float*)d_in[3];
    const float* b_ih    = (const float*)d_in[4];
    const float* b_hh    = (const float*)d_in[5];
    const float* fc_w    = (const float*)d_in[6];
    const float* fc_b    = (const float*)d_in[7];
    const float* fc2_w   = (const float*)d_in[8];
    const float* fc2_b   = (const float*)d_in[9];
    float* out = (float*)d_out;

    reset_counter_kernel<<<1, 1>>>();
    bilstm_kernel<<<GRID, THREADS>>>(x, lengths, w_ih, w_hh, b_ih, b_hh,
                                     fc_w, fc_b, fc2_w, fc2_b, out);
}

// round 4
// speedup vs baseline: 2.5879x; 2.5879x over previous
#include <cuda_runtime.h>
#include <cstdint>

#define B_SIZE 4096
#define T_LEN  2048
#define H_DIM  32
#define THREADS 128
#define WARPS  (THREADS/32)
#define GRID   456

typedef unsigned long long ull;

__device__ int g_task_counter;
__device__ int g_order[B_SIZE];

// ---- packed f32x2 helpers ----
__device__ __forceinline__ ull pk2(float a, float b) {
    ull r; asm("mov.b64 %0, {%1, %2};" : "=l"(r) : "f"(a), "f"(b)); return r;
}
__device__ __forceinline__ void upk2(ull v, float& a, float& b) {
    asm("mov.b64 {%0, %1}, %2;" : "=f"(a), "=f"(b) : "l"(v));
}
__device__ __forceinline__ void ffma2(ull& d, ull a, ull b) {
    asm("fma.rn.f32x2 %0, %1, %2, %0;" : "+l"(d) : "l"(a), "l"(b));
}

// ---- fast transcendentals (MUFU) ----
__device__ __forceinline__ float ex2f(float x) {
    float r; asm("ex2.approx.f32 %0, %1;" : "=f"(r) : "f"(x)); return r;
}
__device__ __forceinline__ float rcpf(float x) {
    float r; asm("rcp.approx.f32 %0, %1;" : "=f"(r) : "f"(x)); return r;
}
#define L2E 1.4426950408889634f
__device__ __forceinline__ float sigf(float z)  { return rcpf(1.f + ex2f(-L2E * z)); }
__device__ __forceinline__ float tanhf_(float z){ return fmaf(-2.f, rcpf(1.f + ex2f(2.f * L2E * z)), 1.f); }

// ---- LPT scheduler: order tasks longest-first (16-step buckets) ----
__global__ void __launch_bounds__(128)
schedule_kernel(const int* __restrict__ lengths)
{
    __shared__ int s_hist[128];
    __shared__ int s_base[128];
    const int tid = threadIdx.x;
    s_hist[tid] = 0;
    __syncthreads();
    for (int i = tid; i < B_SIZE; i += 128) {
        int b = (T_LEN - lengths[i]) >> 4;   // bucket 0 = longest
        atomicAdd(&s_hist[b], 1);
    }
    __syncthreads();
    if (tid == 0) {
        int acc = 0;
        for (int b = 0; b < 128; b++) { s_base[b] = acc; acc += s_hist[b]; }
        g_task_counter = 0;
    }
    __syncthreads();
    s_hist[tid] = 0;
    __syncthreads();
    for (int i = tid; i < B_SIZE; i += 128) {
        int b = (T_LEN - lengths[i]) >> 4;
        int pos = s_base[b] + atomicAdd(&s_hist[b], 1);
        g_order[pos] = i;
    }
}

__global__ void __launch_bounds__(THREADS, 3)
bilstm_kernel(const float* __restrict__ x,
              const int*   __restrict__ lengths,
              const float* __restrict__ w_ih,
              const float* __restrict__ w_hh,
              const float* __restrict__ b_ih,
              const float* __restrict__ b_hh,
              const float* __restrict__ fc_w,
              const float* __restrict__ fc_b,
              const float* __restrict__ fc2_w,
              const float* __restrict__ fc2_b,
              float* __restrict__ out)
{
    __shared__ __align__(16) float s_h[WARPS * 64];  // per-warp double-buffered h

    const int tid  = threadIdx.x;
    const int lane = tid & 31;
    const int wid  = tid >> 5;

    // ---- per-lane recurrent weights in registers (loaded once) ----
    const int l = lane;
    const float bci = b_ih[l]      + b_hh[l];
    const float bcf = b_ih[32 + l] + b_hh[32 + l];
    const float bcg = b_ih[64 + l] + b_hh[64 + l];
    const float bco = b_ih[96 + l] + b_hh[96 + l];
    const float wxi = w_ih[l], wxf = w_ih[32 + l], wxg = w_ih[64 + l], wxo = w_ih[96 + l];

    ull wI[16], wF[16], wG[16], wO[16];
    {
        const ull* pI = (const ull*)(w_hh + (0  + l) * H_DIM);
        const ull* pF = (const ull*)(w_hh + (32 + l) * H_DIM);
        const ull* pG = (const ull*)(w_hh + (64 + l) * H_DIM);
        const ull* pO = (const ull*)(w_hh + (96 + l) * H_DIM);
        #pragma unroll
        for (int j = 0; j < 16; j++) { wI[j] = pI[j]; wF[j] = pF[j]; wG[j] = pG[j]; wO[j] = pO[j]; }
    }

    float* hb = s_h + wid * 64;

    // ---- dynamic task loop: one warp = one sequence at a time (LPT order) ----
    for (;;) {
        unsigned tk = 0;
        if (lane == 0) tk = (unsigned)atomicAdd(&g_task_counter, 1);
        tk = __shfl_sync(0xffffffffu, tk, 0);
        if (tk >= B_SIZE) break;
        const int task = g_order[tk];

        const int len = lengths[task];
        const float* xb = x + (size_t)task * T_LEN;

        float c = 0.f;
        int pb = 0;
        hb[lane] = 0.f;
        __syncwarp();

        int t = len - 1;
        float xv = __ldg(xb + t);
        while (t >= 0) {
            const int tn = (t > 0) ? (t - 1) : 0;
            float xn = __ldg(xb + tn);   // prefetch next x off the critical chain

            // gate accumulators: (even-k partial, odd-k partial)
            ull ai = pk2(fmaf(xv, wxi, bci), 0.f);
            ull af = pk2(fmaf(xv, wxf, bcf), 0.f);
            ull ag = pk2(fmaf(xv, wxg, bcg), 0.f);
            ull ao = pk2(fmaf(xv, wxo, bco), 0.f);

            const ulonglong2* hp = (const ulonglong2*)(hb + pb);
            #pragma unroll
            for (int j = 0; j < 8; j++) {
                ulonglong2 q = hp[j];   // (h[4j],h[4j+1]) , (h[4j+2],h[4j+3])
                ffma2(ai, wI[2*j],     q.x); ffma2(af, wF[2*j],     q.x);
                ffma2(ag, wG[2*j],     q.x); ffma2(ao, wO[2*j],     q.x);
                ffma2(ai, wI[2*j + 1], q.y); ffma2(af, wF[2*j + 1], q.y);
                ffma2(ag, wG[2*j + 1], q.y); ffma2(ao, wO[2*j + 1], q.y);
            }
            float e0, e1;
            upk2(ai, e0, e1); const float gi = e0 + e1;
            upk2(af, e0, e1); const float gf = e0 + e1;
            upk2(ag, e0, e1); const float gg = e0 + e1;
            upk2(ao, e0, e1); const float go = e0 + e1;

            const float iv = sigf(gi);
            const float fv = sigf(gf);
            const float gv = tanhf_(gg);
            const float ov = sigf(go);
            c = fmaf(fv, c, iv * gv);
            const float hn = ov * tanhf_(c);

            pb ^= 32;
            hb[pb + lane] = hn;
            __syncwarp();
            xv = xn;
            --t;
        }

        // ---- FC head (cold path: weights read straight from global) ----
        {
            float u0 = __ldg(fc_b + lane);
            float u1 = __ldg(fc_b + 32 + lane);
            #pragma unroll
            for (int k = 0; k < 32; k++) {
                const float hk = hb[pb + k];              // broadcast read
                u0 = fmaf(__ldg(fc_w + lane * 32 + k),        hk, u0);
                u1 = fmaf(__ldg(fc_w + (32 + lane) * 32 + k), hk, u1);
            }
            u0 = (u0 > 0.f) ? u0 : (ex2f(L2E * u0) - 1.f);
            u1 = (u1 > 0.f) ? u1 : (ex2f(L2E * u1) - 1.f);

            float part = u0 * __ldg(fc2_w + lane) + u1 * __ldg(fc2_w + 32 + lane);
            #pragma unroll
            for (int s = 16; s; s >>= 1) part += __shfl_xor_sync(0xffffffffu, part, s);
            if (lane == 0) out[task] = sigf(part + __ldg(fc2_b));
            __syncwarp();   // protect hb reuse across tasks
        }
    }
}

extern "C" void kernel_launch(void* const* d_in, const int* in_sizes, int n_in,
                              void* d_out, int out_size)
{
    const float* x       = (const float*)d_in[0];
    const int*   lengths = (const int*)  d_in[1];
    const float* w_ih    = (const float*)d_in[2];
    const float* w_hh    = (const float*)d_in[3];
    const float* b_ih    = (const float*)d_in[4];
    const float* b_hh    = (const float*)d_in[5];
    const float* fc_w    = (const float*)d_in[6];
    const float* fc_b    = (const float*)d_in[7];
    const float* fc2_w   = (const float*)d_in[8];
    const float* fc2_b   = (const float*)d_in[9];
    float* out = (float*)d_out;

    schedule_kernel<<<1, 128>>>(lengths);
    bilstm_kernel<<<GRID, THREADS>>>(x, lengths, w_ih, w_hh, b_ih, b_hh,
                                     fc_w, fc_b, fc2_w, fc2_b, out);
}